// round 5
// baseline (speedup 1.0000x reference)
#include <cuda_runtime.h>
#include <cuda_bf16.h>
#include <float.h>
#include <stdint.h>

#define Bb 4
#define Cc 256
#define C8 32
#define Hh 64
#define Ww 64
#define HW 4096

// ===================== helpers =============================================
__device__ __forceinline__ uint32_t smem_u32(const void* p) {
    uint32_t a;
    asm("{ .reg .u64 t; cvta.to.shared.u64 t, %1; cvt.u32.u64 %0, t; }"
        : "=r"(a) : "l"(p));
    return a;
}
#define SWZ64(off) ((off) ^ (((off) >> 3) & 0x30))

__device__ __forceinline__ void ldsm_x4(uint32_t (&r)[4], uint32_t addr) {
    asm volatile("ldmatrix.sync.aligned.m8n8.x4.shared.b16 {%0,%1,%2,%3}, [%4];"
                 : "=r"(r[0]), "=r"(r[1]), "=r"(r[2]), "=r"(r[3]) : "r"(addr));
}

__device__ __forceinline__ void mma_s8(int (&d)[4], const uint32_t (&a)[4],
                                       uint32_t b0, uint32_t b1) {
    asm volatile(
        "mma.sync.aligned.m16n8k32.row.col.s32.s8.s8.s32 "
        "{%0,%1,%2,%3}, {%4,%5,%6,%7}, {%8,%9}, {%0,%1,%2,%3};"
        : "+r"(d[0]), "+r"(d[1]), "+r"(d[2]), "+r"(d[3])
        : "r"(a[0]), "r"(a[1]), "r"(a[2]), "r"(a[3]), "r"(b0), "r"(b1));
}

#define CP_ASYNC16(dst, src) \
    asm volatile("cp.async.cg.shared.global [%0], [%1], 16;" :: "r"(dst), "l"(src) : "memory")
#define CP_COMMIT()  asm volatile("cp.async.commit_group;" ::: "memory")
#define CP_WAIT1()   asm volatile("cp.async.wait_group 1;" ::: "memory")

// ===================== scratch =============================================
__device__ float g_q[Bb * C8 * HW];
__device__ float g_k[Bb * C8 * HW];
__device__ float g_vt[Bb * HW * Cc];          // NHWC value: [b][p][c]
__device__ float g_pmax[Bb * 4 * HW];
__device__ int   g_parg[Bb * 4 * HW];
__device__ float g_S[Bb * HW];
__device__ int   g_arg[Bb * HW];
// int8 planes, NHWC with zero halo: [B][66][66][512]
__device__ int8_t g_Xh[(size_t)Bb * 66 * 66 * 512];
__device__ int8_t g_Xl[(size_t)Bb * 66 * 66 * 512];
// weights: [tap9][o 256][c 512]
__device__ int8_t g_Wh[9 * 256 * 512];
__device__ int8_t g_Wl[9 * 256 * 512];

// ===================== 1x1 GEMM (q,k projections, NCHW out) ================
__global__ __launch_bounds__(256) void gemm1x1(const float* __restrict__ X,
                                               const float* __restrict__ Wm,
                                               const float* __restrict__ bias,
                                               float* __restrict__ out, int O) {
    __shared__ float Xs[16][128];
    __shared__ float Ws[16][36];
    const int b   = blockIdx.z;
    const int o0  = blockIdx.y * 32;
    const int hw0 = blockIdx.x * 128;
    const int tid = threadIdx.x;
    const int hid = tid & 31;
    const int oid = tid >> 5;

    const float* xb = X + (size_t)b * Cc * HW;
    float acc[4][4];
#pragma unroll
    for (int n = 0; n < 4; n++)
#pragma unroll
        for (int m = 0; m < 4; m++) acc[n][m] = 0.f;

    for (int c0 = 0; c0 < Cc; c0 += 16) {
        __syncthreads();
#pragma unroll
        for (int r = 0; r < 8; r++) {
            int idx = tid + r * 256;
            int cc = idx >> 7, h = idx & 127;
            Xs[cc][h] = xb[(size_t)(c0 + cc) * HW + hw0 + h];
        }
#pragma unroll
        for (int r = 0; r < 2; r++) {
            int idx = tid + r * 256;
            int cc = idx >> 5, o = idx & 31;
            Ws[cc][o] = Wm[(size_t)(o0 + o) * Cc + c0 + cc];
        }
        __syncthreads();
#pragma unroll
        for (int cc = 0; cc < 16; cc++) {
            float4 wv = *(const float4*)&Ws[cc][oid * 4];
            float4 xv = *(const float4*)&Xs[cc][hid * 4];
            float wa[4] = {wv.x, wv.y, wv.z, wv.w};
            float xa[4] = {xv.x, xv.y, xv.z, xv.w};
#pragma unroll
            for (int n = 0; n < 4; n++)
#pragma unroll
                for (int m = 0; m < 4; m++) acc[n][m] += wa[n] * xa[m];
        }
    }
#pragma unroll
    for (int n = 0; n < 4; n++) {
        int o = o0 + oid * 4 + n;
        float bi = bias[o];
        float4 res;
        res.x = acc[n][0] + bi;
        res.y = acc[n][1] + bi;
        res.z = acc[n][2] + bi;
        res.w = acc[n][3] + bi;
        *(float4*)&out[(size_t)b * O * HW + (size_t)o * HW + hw0 + hid * 4] = res;
    }
}

// ===================== v projection with NHWC output =======================
__global__ __launch_bounds__(256) void gemm1x1_nhwc(const float* __restrict__ X,
                                                    const float* __restrict__ Wm,
                                                    const float* __restrict__ bias,
                                                    float* __restrict__ vt) {
    __shared__ float Xs[16][128];
    __shared__ float Ws[16][36];
    __shared__ float Ts[128][33];
    const int b   = blockIdx.z;
    const int o0  = blockIdx.y * 32;
    const int hw0 = blockIdx.x * 128;
    const int tid = threadIdx.x;
    const int hid = tid & 31;
    const int oid = tid >> 5;

    const float* xb = X + (size_t)b * Cc * HW;
    float acc[4][4];
#pragma unroll
    for (int n = 0; n < 4; n++)
#pragma unroll
        for (int m = 0; m < 4; m++) acc[n][m] = 0.f;

    for (int c0 = 0; c0 < Cc; c0 += 16) {
        __syncthreads();
#pragma unroll
        for (int r = 0; r < 8; r++) {
            int idx = tid + r * 256;
            int cc = idx >> 7, h = idx & 127;
            Xs[cc][h] = xb[(size_t)(c0 + cc) * HW + hw0 + h];
        }
#pragma unroll
        for (int r = 0; r < 2; r++) {
            int idx = tid + r * 256;
            int cc = idx >> 5, o = idx & 31;
            Ws[cc][o] = Wm[(size_t)(o0 + o) * Cc + c0 + cc];
        }
        __syncthreads();
#pragma unroll
        for (int cc = 0; cc < 16; cc++) {
            float4 wv = *(const float4*)&Ws[cc][oid * 4];
            float4 xv = *(const float4*)&Xs[cc][hid * 4];
            float wa[4] = {wv.x, wv.y, wv.z, wv.w};
            float xa[4] = {xv.x, xv.y, xv.z, xv.w};
#pragma unroll
            for (int n = 0; n < 4; n++)
#pragma unroll
                for (int m = 0; m < 4; m++) acc[n][m] += wa[n] * xa[m];
        }
    }
    // transpose through smem, write [p][c]
    __syncthreads();
#pragma unroll
    for (int n = 0; n < 4; n++) {
        float bi = bias[o0 + oid * 4 + n];
#pragma unroll
        for (int m = 0; m < 4; m++) Ts[hid * 4 + m][oid * 4 + n] = acc[n][m] + bi;
    }
    __syncthreads();
    {
        const int hwl = tid >> 1;
        const int og  = (tid & 1) * 16;
        float* dst = vt + ((size_t)b * HW + hw0 + hwl) * Cc + o0 + og;
#pragma unroll
        for (int i = 0; i < 4; i++) {
            float4 v;
            v.x = Ts[hwl][og + 4 * i];
            v.y = Ts[hwl][og + 4 * i + 1];
            v.z = Ts[hwl][og + 4 * i + 2];
            v.w = Ts[hwl][og + 4 * i + 3];
            *(float4*)(dst + 4 * i) = v;
        }
    }
}

// ===================== energy rowmax/argmax (exact fp32) ====================
__global__ __launch_bounds__(128) void energy_argmax() {
    __shared__ float ks[32][128];
    const int b  = blockIdx.y;
    const int j  = blockIdx.x * 128 + threadIdx.x;
    const int sp = blockIdx.z;
    const float* qb = g_q + (size_t)b * C8 * HW;
    const float* kb = g_k + (size_t)b * C8 * HW;

    float qr[32];
#pragma unroll
    for (int c = 0; c < 32; c++) qr[c] = qb[c * HW + j];

    float best = -FLT_MAX;
    int   barg = 0;
    const int i0base = sp * 1024;

    for (int it = 0; it < 8; it++) {
        int i0 = i0base + it * 128;
        __syncthreads();
#pragma unroll
        for (int c = 0; c < 32; c++) ks[c][threadIdx.x] = kb[c * HW + i0 + threadIdx.x];
        __syncthreads();
#pragma unroll 4
        for (int ii = 0; ii < 128; ii += 4) {
            float a0 = 0.f, a1 = 0.f, a2 = 0.f, a3 = 0.f;
#pragma unroll
            for (int c = 0; c < 32; c++) {
                float4 kv = *(const float4*)&ks[c][ii];
                a0 += kv.x * qr[c];
                a1 += kv.y * qr[c];
                a2 += kv.z * qr[c];
                a3 += kv.w * qr[c];
            }
            if (a0 > best) { best = a0; barg = i0 + ii; }
            if (a1 > best) { best = a1; barg = i0 + ii + 1; }
            if (a2 > best) { best = a2; barg = i0 + ii + 2; }
            if (a3 > best) { best = a3; barg = i0 + ii + 3; }
        }
    }
    g_pmax[((size_t)b * 4 + sp) * HW + j] = best;
    g_parg[((size_t)b * 4 + sp) * HW + j] = barg;
}

__global__ void reduce_argmax() {
    int t = blockIdx.x * 256 + threadIdx.x;
    if (t >= Bb * HW) return;
    int b = t >> 12, j = t & 4095;
    float best = g_pmax[((size_t)b * 4) * HW + j];
    int   arg  = g_parg[((size_t)b * 4) * HW + j];
#pragma unroll
    for (int sp = 1; sp < 4; sp++) {
        float e = g_pmax[((size_t)b * 4 + sp) * HW + j];
        if (e > best) { best = e; arg = g_parg[((size_t)b * 4 + sp) * HW + j]; }
    }
    g_S[t] = best;
    g_arg[t] = arg;
}

// ===================== int8 prep ===========================================
__global__ void zero_x8() {
    size_t i = (size_t)blockIdx.x * 256 + threadIdx.x;   // 1,115,136 uint4
    const size_t half = (size_t)Bb * 66 * 66 * 512 / 16; // 557,568
    if (i < half) ((uint4*)g_Xh)[i] = make_uint4(0, 0, 0, 0);
    else          ((uint4*)g_Xl)[i - half] = make_uint4(0, 0, 0, 0);
}

__device__ __forceinline__ void quant16(float v, int& hi, int& lo) {
    int q = __float2int_rn(v * 4096.f);
    q = max(-32256, min(32256, q));
    lo = (int)(int8_t)(q & 0xFF);
    hi = (q - lo) >> 8;
}

// fill X planes: front_x channels 0-255, gathered T channels 256-511
__global__ __launch_bounds__(256) void fill_x8(const float* __restrict__ front_x) {
    __shared__ float sm[32][65];
    const int c0 = blockIdx.x * 32;
    const int y  = blockIdx.y;
    const int b  = blockIdx.z;
    const int tid = threadIdx.x;
    const int x  = tid >> 2;
    const int g  = tid & 3;

    float vals[8];
    if (c0 < 256) {
#pragma unroll
        for (int pass = 0; pass < 8; pass++) {
            int idx = tid + pass * 256;
            int cc = idx >> 6, xx = idx & 63;
            sm[cc][xx] = front_x[((size_t)b * Cc + c0 + cc) * HW + y * Ww + xx];
        }
        __syncthreads();
#pragma unroll
        for (int e = 0; e < 8; e++) vals[e] = sm[g * 8 + e][x];
    } else {
        const int a = g_arg[b * HW + y * Ww + x];
        const float* vp = g_vt + ((size_t)b * HW + a) * Cc + (c0 - 256) + g * 8;
        float4 u0 = *(const float4*)vp;
        float4 u1 = *(const float4*)(vp + 4);
        vals[0] = u0.x; vals[1] = u0.y; vals[2] = u0.z; vals[3] = u0.w;
        vals[4] = u1.x; vals[5] = u1.y; vals[6] = u1.z; vals[7] = u1.w;
    }

    unsigned long long hb = 0ULL, lb = 0ULL;
#pragma unroll
    for (int e = 0; e < 8; e++) {
        int hi, lo;
        quant16(vals[e], hi, lo);
        hb |= ((unsigned long long)(uint8_t)hi) << (8 * e);
        lb |= ((unsigned long long)(uint8_t)lo) << (8 * e);
    }
    const size_t base = ((size_t)(b * 66 + y + 1) * 66 + (x + 1)) * 512 + c0 + g * 8;
    *(unsigned long long*)&g_Xh[base] = hb;
    *(unsigned long long*)&g_Xl[base] = lb;
}

// weights: Wf(O=256, I=512, 3,3) -> planes [tap][o][i]
__global__ void prep_w8(const float* __restrict__ Wf) {
    int t = blockIdx.x * 256 + threadIdx.x;       // 131072
    int o = t >> 9, i = t & 511;
#pragma unroll
    for (int k = 0; k < 9; k++) {
        float w = Wf[((size_t)o * 512 + i) * 9 + k];
        int q = __float2int_rn(w * 262144.f);
        q = max(-32256, min(32256, q));
        int lo = (int)(int8_t)(q & 0xFF);
        int hi = (q - lo) >> 8;
        size_t off = ((size_t)k * 256 + o) * 512 + i;
        g_Wh[off] = (int8_t)hi;
        g_Wl[off] = (int8_t)lo;
    }
}

// ===================== int8 mma conv3x3 + fused epilogue ====================
// CTA: M=128 out-ch x N=128 px (2 rows). 8 warps = 4(M) x 2(N).
// K: 9 taps x 8 chunks of 64 ch; per chunk stage 4 tiles 128x64 s8 (8KB, SW64)
// via cp.async, 3-stage pipeline (32KB/stage).
#define STAGE8 32768
#define NCHUNK 72

__device__ __forceinline__ void stage_chunk8(uint32_t stg, int s, int b, int y0, int m0) {
    const int tap = s >> 3, kc = (s & 7) * 64;
    const int dy = tap / 3, dx = tap % 3;
    const int tid = threadIdx.x;
#pragma unroll
    for (int i = 0; i < 8; i++) {
        const int t = i >> 1;                     // 0:Bh 1:Bl 2:Ah 3:Al
        const int c = ((i & 1) << 8) + tid;       // 0..511
        const int r = c >> 2, c16 = c & 3;
        uint32_t dst = stg + (uint32_t)(t * 8192) + SWZ64((uint32_t)(r * 64 + c16 * 16));
        const void* src;
        if (t < 2) {
            const int ry = r >> 6, x = r & 63;
            const int8_t* plane = (t == 0) ? g_Xh : g_Xl;
            src = plane + ((size_t)(b * 66 + y0 + ry + dy) * 66 + (x + dx)) * 512
                        + kc + c16 * 16;
        } else {
            const int8_t* plane = (t == 2) ? g_Wh : g_Wl;
            src = plane + ((size_t)tap * 256 + m0 + r) * 512 + kc + c16 * 16;
        }
        CP_ASYNC16(dst, src);
    }
    CP_COMMIT();
}

__global__ __launch_bounds__(256, 1) void conv_mma8(const float* __restrict__ front_x,
                                                    const float* __restrict__ bf,
                                                    float* __restrict__ out) {
    extern __shared__ char dynsm[];
    const int tid  = threadIdx.x;
    const int lane = tid & 31;
    const int wid  = tid >> 5;
    const int wm   = wid & 3;
    const int wn   = wid >> 2;
    const int nt   = blockIdx.x;
    const int m0   = blockIdx.y * 128;
    const int b    = blockIdx.z;
    const int y0   = nt * 2;
    const int n0   = nt * 128;

    const uint32_t smbase = smem_u32(dynsm);

    int hh[2][8][4], mm_[2][8][4];
#pragma unroll
    for (int mt = 0; mt < 2; mt++)
#pragma unroll
        for (int j = 0; j < 8; j++)
#pragma unroll
            for (int e = 0; e < 4; e++) { hh[mt][j][e] = 0; mm_[mt][j][e] = 0; }

    const uint32_t arow  = wm * 32 + (lane & 15);
    const uint32_t acolh = (lane >> 4) * 16;
    const uint32_t brow  = wn * 64 + (lane & 7) + ((lane >> 4) << 3);
    const uint32_t bcolh = ((lane >> 3) & 1) * 16;

    stage_chunk8(smbase, 0, b, y0, m0);
    stage_chunk8(smbase + STAGE8, 1, b, y0, m0);

    for (int s = 0; s < NCHUNK; s++) {
        CP_WAIT1();
        __syncthreads();
        if (s + 2 < NCHUNK) {
            int nb = (s + 2) % 3;
            stage_chunk8(smbase + nb * STAGE8, s + 2, b, y0, m0);
        }

        const uint32_t base = smbase + (s % 3) * STAGE8;
        const uint32_t tBh = base, tBl = base + 8192;
        const uint32_t tAh = base + 16384, tAl = base + 24576;

#pragma unroll
        for (int ks = 0; ks < 2; ks++) {
            uint32_t ah[2][4], al[2][4];
#pragma unroll
            for (int mt = 0; mt < 2; mt++) {
                uint32_t off = SWZ64((arow + mt * 16) * 64 + ks * 32 + acolh);
                ldsm_x4(ah[mt], tAh + off);
                ldsm_x4(al[mt], tAl + off);
            }
#pragma unroll
            for (int j = 0; j < 4; j++) {
                uint32_t bh[4], bl[4];
                uint32_t off = SWZ64((brow + j * 16) * 64 + ks * 32 + bcolh);
                ldsm_x4(bh, tBh + off);
                ldsm_x4(bl, tBl + off);
#pragma unroll
                for (int mt = 0; mt < 2; mt++) {
                    mma_s8(hh[mt][2 * j],      ah[mt], bh[0], bh[1]);
                    mma_s8(hh[mt][2 * j + 1],  ah[mt], bh[2], bh[3]);
                    mma_s8(mm_[mt][2 * j],     ah[mt], bl[0], bl[1]);
                    mma_s8(mm_[mt][2 * j + 1], ah[mt], bl[2], bl[3]);
                    mma_s8(mm_[mt][2 * j],     al[mt], bh[0], bh[1]);
                    mma_s8(mm_[mt][2 * j + 1], al[mt], bh[2], bh[3]);
                }
            }
        }
        __syncthreads();
    }

    // epilogue: res = (65536*hh + 256*mm) / 2^30 ; out = front_x + (res+bf)*S
    const float inv30 = 9.313225746154785e-10f;
    const float* Sb = g_S + (size_t)b * HW;
#pragma unroll
    for (int mt = 0; mt < 2; mt++) {
        const int o_lo = m0 + wm * 32 + mt * 16 + (lane >> 2);
        const int o_hi = o_lo + 8;
        const float bi_lo = bf[o_lo], bi_hi = bf[o_hi];
#pragma unroll
        for (int j = 0; j < 8; j++) {
            const int p = n0 + wn * 64 + j * 8 + 2 * (lane & 3);
            const float2 Sv = *(const float2*)&Sb[p];
            const size_t off0 = ((size_t)(b * Cc + o_lo)) * HW + p;
            const size_t off1 = ((size_t)(b * Cc + o_hi)) * HW + p;
            const float2 f0 = *(const float2*)&front_x[off0];
            const float2 f1 = *(const float2*)&front_x[off1];
            float r[4];
#pragma unroll
            for (int e = 0; e < 4; e++)
                r[e] = fmaf(65536.f, (float)hh[mt][j][e], 256.f * (float)mm_[mt][j][e]) * inv30;
            float2 r0, r1;
            r0.x = f0.x + (r[0] + bi_lo) * Sv.x;
            r0.y = f0.y + (r[1] + bi_lo) * Sv.y;
            r1.x = f1.x + (r[2] + bi_hi) * Sv.x;
            r1.y = f1.y + (r[3] + bi_hi) * Sv.y;
            *(float2*)&out[off0] = r0;
            *(float2*)&out[off1] = r1;
        }
    }
}

// ===================== launch ==============================================
extern "C" void kernel_launch(void* const* d_in, const int* in_sizes, int n_in,
                              void* d_out, int out_size) {
    const float* front_x     = (const float*)d_in[0];
    const float* cross_x     = (const float*)d_in[1];
    const float* front_x_hat = (const float*)d_in[2];
    const float* Wq = (const float*)d_in[3];
    const float* bq = (const float*)d_in[4];
    const float* Wk = (const float*)d_in[5];
    const float* bk = (const float*)d_in[6];
    const float* Wv = (const float*)d_in[7];
    const float* bv = (const float*)d_in[8];
    const float* Wf = (const float*)d_in[9];
    const float* bf = (const float*)d_in[10];
    float* out = (float*)d_out;

    cudaFuncSetAttribute(conv_mma8, cudaFuncAttributeMaxDynamicSharedMemorySize, 3 * STAGE8);

    float *q, *k, *vt;
    cudaGetSymbolAddress((void**)&q, g_q);
    cudaGetSymbolAddress((void**)&k, g_k);
    cudaGetSymbolAddress((void**)&vt, g_vt);

    zero_x8<<<4356, 256>>>();
    prep_w8<<<512, 256>>>(Wf);

    gemm1x1<<<dim3(32, 1, 4), 256>>>(cross_x, Wq, bq, q, C8);
    gemm1x1<<<dim3(32, 1, 4), 256>>>(front_x, Wk, bk, k, C8);
    gemm1x1_nhwc<<<dim3(32, 8, 4), 256>>>(front_x_hat, Wv, bv, vt);

    energy_argmax<<<dim3(32, 4, 4), 128>>>();
    reduce_argmax<<<64, 256>>>();

    fill_x8<<<dim3(16, 64, 4), 256>>>(front_x);

    conv_mma8<<<dim3(32, 2, 4), 256, 3 * STAGE8>>>(front_x, bf, out);
}

// round 6
// speedup vs baseline: 2.1206x; 2.1206x over previous
#include <cuda_runtime.h>
#include <cuda_bf16.h>
#include <float.h>
#include <stdint.h>

#define Bb 4
#define Cc 256
#define C8 32
#define Hh 64
#define Ww 64
#define HW 4096

// ===================== helpers =============================================
__device__ __forceinline__ uint32_t smem_u32(const void* p) {
    uint32_t a;
    asm("{ .reg .u64 t; cvta.to.shared.u64 t, %1; cvt.u32.u64 %0, t; }"
        : "=r"(a) : "l"(p));
    return a;
}
#define SWZ128(off) ((off) ^ (((off) >> 3) & 0x70))

__device__ __forceinline__ void ldsm_x4(uint32_t (&r)[4], uint32_t addr) {
    asm volatile("ldmatrix.sync.aligned.m8n8.x4.shared.b16 {%0,%1,%2,%3}, [%4];"
                 : "=r"(r[0]), "=r"(r[1]), "=r"(r[2]), "=r"(r[3]) : "r"(addr));
}

__device__ __forceinline__ void mma_bf16(float (&d)[4], const uint32_t (&a)[4],
                                         uint32_t b0, uint32_t b1) {
    asm volatile(
        "mma.sync.aligned.m16n8k16.row.col.f32.bf16.bf16.f32 "
        "{%0,%1,%2,%3}, {%4,%5,%6,%7}, {%8,%9}, {%0,%1,%2,%3};"
        : "+f"(d[0]), "+f"(d[1]), "+f"(d[2]), "+f"(d[3])
        : "r"(a[0]), "r"(a[1]), "r"(a[2]), "r"(a[3]), "r"(b0), "r"(b1));
}

#define CP_ASYNC16(dst, src) \
    asm volatile("cp.async.cg.shared.global [%0], [%1], 16;" :: "r"(dst), "l"(src) : "memory")
#define CP_COMMIT()  asm volatile("cp.async.commit_group;" ::: "memory")
#define CP_WAIT1()   asm volatile("cp.async.wait_group 1;" ::: "memory")

// ===================== scratch =============================================
__device__ float g_q[Bb * C8 * HW];
__device__ float g_k[Bb * C8 * HW];
__device__ float g_vt[Bb * HW * Cc];          // NHWC value: [b][p][c]
__device__ float g_pmax[Bb * 4 * HW];
__device__ int   g_parg[Bb * 4 * HW];
__device__ float g_S[Bb * HW];
__device__ int   g_arg[Bb * HW];
// NHWC bf16, zero halo: [B][66][66][hi 512 | lo 512]
__device__ __nv_bfloat16 g_Xt[(size_t)Bb * 66 * 66 * 1024];
// weights split: [seg(hi0/lo1)][tap9][o 256][c 512] bf16
__device__ __nv_bfloat16 g_Wa[2 * 9 * 256 * 512];

// ===================== fused q+k projection (O=32 each) =====================
__global__ __launch_bounds__(256) void gemm_qk(const float* __restrict__ cross_x,
                                               const float* __restrict__ front_x,
                                               const float* __restrict__ Wq,
                                               const float* __restrict__ bq,
                                               const float* __restrict__ Wk,
                                               const float* __restrict__ bk) {
    __shared__ float Xs[16][128];
    __shared__ float Ws[16][36];
    const int b   = blockIdx.z;
    const int sel = blockIdx.y;                 // 0 -> q, 1 -> k
    const int hw0 = blockIdx.x * 128;
    const int tid = threadIdx.x;
    const int hid = tid & 31;
    const int oid = tid >> 5;

    const float* X    = sel ? front_x : cross_x;
    const float* Wm   = sel ? Wk : Wq;
    const float* bias = sel ? bk : bq;
    float*       out  = sel ? g_k : g_q;

    const float* xb = X + (size_t)b * Cc * HW;
    float acc[4][4];
#pragma unroll
    for (int n = 0; n < 4; n++)
#pragma unroll
        for (int m = 0; m < 4; m++) acc[n][m] = 0.f;

    for (int c0 = 0; c0 < Cc; c0 += 16) {
        __syncthreads();
#pragma unroll
        for (int r = 0; r < 8; r++) {
            int idx = tid + r * 256;
            int cc = idx >> 7, h = idx & 127;
            Xs[cc][h] = xb[(size_t)(c0 + cc) * HW + hw0 + h];
        }
#pragma unroll
        for (int r = 0; r < 2; r++) {
            int idx = tid + r * 256;
            int cc = idx >> 5, o = idx & 31;
            Ws[cc][o] = Wm[(size_t)o * Cc + c0 + cc];
        }
        __syncthreads();
#pragma unroll
        for (int cc = 0; cc < 16; cc++) {
            float4 wv = *(const float4*)&Ws[cc][oid * 4];
            float4 xv = *(const float4*)&Xs[cc][hid * 4];
            float wa[4] = {wv.x, wv.y, wv.z, wv.w};
            float xa[4] = {xv.x, xv.y, xv.z, xv.w};
#pragma unroll
            for (int n = 0; n < 4; n++)
#pragma unroll
                for (int m = 0; m < 4; m++) acc[n][m] += wa[n] * xa[m];
        }
    }
#pragma unroll
    for (int n = 0; n < 4; n++) {
        int o = oid * 4 + n;
        float bi = bias[o];
        float4 res;
        res.x = acc[n][0] + bi;
        res.y = acc[n][1] + bi;
        res.z = acc[n][2] + bi;
        res.w = acc[n][3] + bi;
        *(float4*)&out[(size_t)b * C8 * HW + (size_t)o * HW + hw0 + hid * 4] = res;
    }
}

// ===================== v projection with NHWC output =======================
__global__ __launch_bounds__(256) void gemm1x1_nhwc(const float* __restrict__ X,
                                                    const float* __restrict__ Wm,
                                                    const float* __restrict__ bias,
                                                    float* __restrict__ vt) {
    __shared__ float Xs[16][128];
    __shared__ float Ws[16][36];
    __shared__ float Ts[128][33];
    const int b   = blockIdx.z;
    const int o0  = blockIdx.y * 32;
    const int hw0 = blockIdx.x * 128;
    const int tid = threadIdx.x;
    const int hid = tid & 31;
    const int oid = tid >> 5;

    const float* xb = X + (size_t)b * Cc * HW;
    float acc[4][4];
#pragma unroll
    for (int n = 0; n < 4; n++)
#pragma unroll
        for (int m = 0; m < 4; m++) acc[n][m] = 0.f;

    for (int c0 = 0; c0 < Cc; c0 += 16) {
        __syncthreads();
#pragma unroll
        for (int r = 0; r < 8; r++) {
            int idx = tid + r * 256;
            int cc = idx >> 7, h = idx & 127;
            Xs[cc][h] = xb[(size_t)(c0 + cc) * HW + hw0 + h];
        }
#pragma unroll
        for (int r = 0; r < 2; r++) {
            int idx = tid + r * 256;
            int cc = idx >> 5, o = idx & 31;
            Ws[cc][o] = Wm[(size_t)(o0 + o) * Cc + c0 + cc];
        }
        __syncthreads();
#pragma unroll
        for (int cc = 0; cc < 16; cc++) {
            float4 wv = *(const float4*)&Ws[cc][oid * 4];
            float4 xv = *(const float4*)&Xs[cc][hid * 4];
            float wa[4] = {wv.x, wv.y, wv.z, wv.w};
            float xa[4] = {xv.x, xv.y, xv.z, xv.w};
#pragma unroll
            for (int n = 0; n < 4; n++)
#pragma unroll
                for (int m = 0; m < 4; m++) acc[n][m] += wa[n] * xa[m];
        }
    }
    __syncthreads();
#pragma unroll
    for (int n = 0; n < 4; n++) {
        float bi = bias[o0 + oid * 4 + n];
#pragma unroll
        for (int m = 0; m < 4; m++) Ts[hid * 4 + m][oid * 4 + n] = acc[n][m] + bi;
    }
    __syncthreads();
    {
        const int hwl = tid >> 1;
        const int og  = (tid & 1) * 16;
        float* dst = vt + ((size_t)b * HW + hw0 + hwl) * Cc + o0 + og;
#pragma unroll
        for (int i = 0; i < 4; i++) {
            float4 v;
            v.x = Ts[hwl][og + 4 * i];
            v.y = Ts[hwl][og + 4 * i + 1];
            v.z = Ts[hwl][og + 4 * i + 2];
            v.w = Ts[hwl][og + 4 * i + 3];
            *(float4*)(dst + 4 * i) = v;
        }
    }
}

// ===================== energy rowmax/argmax (exact fp32) ====================
__global__ __launch_bounds__(128) void energy_argmax() {
    __shared__ float ks[32][128];
    const int b  = blockIdx.y;
    const int j  = blockIdx.x * 128 + threadIdx.x;
    const int sp = blockIdx.z;
    const float* qb = g_q + (size_t)b * C8 * HW;
    const float* kb = g_k + (size_t)b * C8 * HW;

    float qr[32];
#pragma unroll
    for (int c = 0; c < 32; c++) qr[c] = qb[c * HW + j];

    float best = -FLT_MAX;
    int   barg = 0;
    const int i0base = sp * 1024;

    for (int it = 0; it < 8; it++) {
        int i0 = i0base + it * 128;
        __syncthreads();
#pragma unroll
        for (int c = 0; c < 32; c++) ks[c][threadIdx.x] = kb[c * HW + i0 + threadIdx.x];
        __syncthreads();
#pragma unroll 4
        for (int ii = 0; ii < 128; ii += 4) {
            float a0 = 0.f, a1 = 0.f, a2 = 0.f, a3 = 0.f;
#pragma unroll
            for (int c = 0; c < 32; c++) {
                float4 kv = *(const float4*)&ks[c][ii];
                a0 += kv.x * qr[c];
                a1 += kv.y * qr[c];
                a2 += kv.z * qr[c];
                a3 += kv.w * qr[c];
            }
            if (a0 > best) { best = a0; barg = i0 + ii; }
            if (a1 > best) { best = a1; barg = i0 + ii + 1; }
            if (a2 > best) { best = a2; barg = i0 + ii + 2; }
            if (a3 > best) { best = a3; barg = i0 + ii + 3; }
        }
    }
    g_pmax[((size_t)b * 4 + sp) * HW + j] = best;
    g_parg[((size_t)b * 4 + sp) * HW + j] = barg;
}

__global__ void reduce_argmax() {
    int t = blockIdx.x * 256 + threadIdx.x;
    if (t >= Bb * HW) return;
    int b = t >> 12, j = t & 4095;
    float best = g_pmax[((size_t)b * 4) * HW + j];
    int   arg  = g_parg[((size_t)b * 4) * HW + j];
#pragma unroll
    for (int sp = 1; sp < 4; sp++) {
        float e = g_pmax[((size_t)b * 4 + sp) * HW + j];
        if (e > best) { best = e; arg = g_parg[((size_t)b * 4 + sp) * HW + j]; }
    }
    g_S[t] = best;
    g_arg[t] = arg;
}

// ===================== conv input prep =====================================
// zero only the halo ring of g_Xt (interior is fully overwritten by fill_xt)
__global__ void zero_halo() {
    // halo pixels per batch: rows 0 and 65 (66 px each) + cols 0 and 65 (64 px each)
    // = 132 + 128 = 260 px, each 1024 bf16 = 64 uint4
    const int t = blockIdx.x * 256 + threadIdx.x;    // 4*260*64 = 66560
    if (t >= Bb * 260 * 64) return;
    const int u = t & 63;
    const int pix = (t >> 6) % 260;
    const int b = t / (260 * 64);
    int y, x;
    if (pix < 66)       { y = 0;        x = pix; }
    else if (pix < 132) { y = 65;       x = pix - 66; }
    else if (pix < 196) { y = pix - 131; x = 0; }     // y=1..64
    else                { y = pix - 195; x = 65; }    // y=1..64
    ((uint4*)g_Xt)[(((size_t)(b * 66 + y) * 66 + x) << 7) + u] = make_uint4(0, 0, 0, 0);
}

// fill interior: front_x channels 0-255 (smem transpose), gathered v 256-511
__global__ __launch_bounds__(256) void fill_xt(const float* __restrict__ front_x) {
    __shared__ float sm[32][65];
    const int c0 = blockIdx.x * 32;      // 16 chunks of 32 channels (0..511)
    const int y  = blockIdx.y;
    const int b  = blockIdx.z;
    const int tid = threadIdx.x;
    const int x  = tid >> 2;
    const int g  = tid & 3;

    float vals[8];
    if (c0 < 256) {
#pragma unroll
        for (int pass = 0; pass < 8; pass++) {
            int idx = tid + pass * 256;
            int cc = idx >> 6, xx = idx & 63;
            sm[cc][xx] = front_x[((size_t)b * Cc + c0 + cc) * HW + y * Ww + xx];
        }
        __syncthreads();
#pragma unroll
        for (int e = 0; e < 8; e++) vals[e] = sm[g * 8 + e][x];
    } else {
        const int a = g_arg[b * HW + y * Ww + x];
        const float* vp = g_vt + ((size_t)b * HW + a) * Cc + (c0 - 256) + g * 8;
        float4 u0 = *(const float4*)vp;
        float4 u1 = *(const float4*)(vp + 4);
        vals[0] = u0.x; vals[1] = u0.y; vals[2] = u0.z; vals[3] = u0.w;
        vals[4] = u1.x; vals[5] = u1.y; vals[6] = u1.z; vals[7] = u1.w;
    }

    uint32_t hu[4], lu[4];
#pragma unroll
    for (int e = 0; e < 4; e++) {
        float v0 = vals[e * 2];
        float v1 = vals[e * 2 + 1];
        __nv_bfloat16 h0 = __float2bfloat16_rn(v0);
        __nv_bfloat16 h1 = __float2bfloat16_rn(v1);
        __nv_bfloat16 l0 = __float2bfloat16_rn(v0 - __bfloat162float(h0));
        __nv_bfloat16 l1 = __float2bfloat16_rn(v1 - __bfloat162float(h1));
        hu[e] = (uint32_t)__bfloat16_as_ushort(h0) | ((uint32_t)__bfloat16_as_ushort(h1) << 16);
        lu[e] = (uint32_t)__bfloat16_as_ushort(l0) | ((uint32_t)__bfloat16_as_ushort(l1) << 16);
    }
    size_t base = ((size_t)(b * 66 + y + 1) * 66 + (x + 1)) * 1024 + c0 + g * 8;
    *(uint4*)&g_Xt[base]       = make_uint4(hu[0], hu[1], hu[2], hu[3]);
    *(uint4*)&g_Xt[base + 512] = make_uint4(lu[0], lu[1], lu[2], lu[3]);
}

// weights: Wf(O=256, I=512, 3,3) -> g_Wa[seg][tap][o][i] bf16 hi/lo
__global__ void prep_w(const float* __restrict__ Wf) {
    int t = blockIdx.x * 256 + threadIdx.x;       // 131072
    int o = t >> 9, i = t & 511;
#pragma unroll
    for (int k = 0; k < 9; k++) {
        float w = Wf[((size_t)o * 512 + i) * 9 + k];
        __nv_bfloat16 h = __float2bfloat16_rn(w);
        __nv_bfloat16 l = __float2bfloat16_rn(w - __bfloat162float(h));
        g_Wa[(((size_t)0 * 9 + k) * 256 + o) * 512 + i] = h;
        g_Wa[(((size_t)1 * 9 + k) * 256 + o) * 512 + i] = l;
    }
}

// ===================== mma.sync conv3x3 + fused epilogue ====================
// CTA: M=128 out-ch x N=128 px (2 rows). 8 warps = 4(M) x 2(N), warp 32x64.
// K loop: 9 taps x 8 chunks of 64ch. Stage/chunk: 4 SW128 tiles of 128x64 bf16
// (Bhi, Blo, Ahi, Alo; 16KB each) via cp.async, 3-stage pipeline (64KB/stage).
#define STAGE 65536
#define NCHUNK 72

__device__ __forceinline__ void stage_chunk(uint32_t stg, int s, int b, int y0, int m0) {
    const int tap = s >> 3, kc = (s & 7) * 64;
    const int dy = tap / 3, dx = tap % 3;
    const int tid = threadIdx.x;
#pragma unroll
    for (int i = 0; i < 16; i++) {
        const int t = i >> 2;                         // 0:Bhi 1:Blo 2:Ahi 3:Alo
        const int c = ((i & 3) << 8) + tid;           // 0..1023
        const int r = c >> 3, c16 = c & 7;
        uint32_t dst = stg + (uint32_t)(t * 16384) + SWZ128((uint32_t)(r * 128 + c16 * 16));
        const void* src;
        if (t < 2) {
            const int ry = r >> 6, x = r & 63;
            src = &g_Xt[(((size_t)(b * 66 + y0 + ry + dy) * 66) + (x + dx)) * 1024
                        + t * 512 + kc + c16 * 8];
        } else {
            src = &g_Wa[(((size_t)((t - 2) * 9 + tap) * 256) + m0 + r) * 512 + kc + c16 * 8];
        }
        CP_ASYNC16(dst, src);
    }
    CP_COMMIT();
}

__global__ __launch_bounds__(256, 1) void conv_mma(const float* __restrict__ front_x,
                                                   const float* __restrict__ bf,
                                                   float* __restrict__ out) {
    extern __shared__ char dynsm[];
    const int tid  = threadIdx.x;
    const int lane = tid & 31;
    const int wid  = tid >> 5;
    const int wm   = wid & 3;                 // M warp (0..3) -> 32 rows
    const int wn   = wid >> 2;                // N warp (0..1) -> 64 px
    const int nt   = blockIdx.x;              // 32 pixel tiles
    const int m0   = blockIdx.y * 128;        // out-ch half
    const int b    = blockIdx.z;
    const int y0   = nt * 2;
    const int n0   = nt * 128;

    const uint32_t smbase = smem_u32(dynsm);

    float acc[2][8][4];
#pragma unroll
    for (int mt = 0; mt < 2; mt++)
#pragma unroll
        for (int j = 0; j < 8; j++)
#pragma unroll
            for (int e = 0; e < 4; e++) acc[mt][j][e] = 0.f;

    const int arow  = wm * 32 + (lane & 15);
    const int acolh = (lane >> 4) * 16;
    const int brow  = wn * 64 + (lane & 7) + ((lane >> 4) << 3);
    const int bcolh = ((lane >> 3) & 1) * 16;

    stage_chunk(smbase, 0, b, y0, m0);
    stage_chunk(smbase + STAGE, 1, b, y0, m0);

    for (int s = 0; s < NCHUNK; s++) {
        CP_WAIT1();
        __syncthreads();
        if (s + 2 < NCHUNK)
            stage_chunk(smbase + ((s + 2) % 3) * STAGE, s + 2, b, y0, m0);

        const uint32_t base = smbase + (s % 3) * STAGE;
        const uint32_t tBhi = base, tBlo = base + 16384;
        const uint32_t tAhi = base + 32768, tAlo = base + 49152;

#pragma unroll
        for (int ks = 0; ks < 4; ks++) {
            uint32_t ah[2][4], al[2][4], bh[4][4], bl[4][4];
#pragma unroll
            for (int mt = 0; mt < 2; mt++) {
                uint32_t off = SWZ128((uint32_t)((arow + mt * 16) * 128 + ks * 32 + acolh));
                ldsm_x4(ah[mt], tAhi + off);
                ldsm_x4(al[mt], tAlo + off);
            }
#pragma unroll
            for (int j = 0; j < 4; j++) {
                uint32_t off = SWZ128((uint32_t)((brow + j * 16) * 128 + ks * 32 + bcolh));
                ldsm_x4(bh[j], tBhi + off);
                ldsm_x4(bl[j], tBlo + off);
            }
#pragma unroll
            for (int mt = 0; mt < 2; mt++)
#pragma unroll
                for (int j = 0; j < 4; j++) {
                    mma_bf16(acc[mt][2 * j],     ah[mt], bh[j][0], bh[j][1]);
                    mma_bf16(acc[mt][2 * j + 1], ah[mt], bh[j][2], bh[j][3]);
                    mma_bf16(acc[mt][2 * j],     al[mt], bh[j][0], bh[j][1]);
                    mma_bf16(acc[mt][2 * j + 1], al[mt], bh[j][2], bh[j][3]);
                    mma_bf16(acc[mt][2 * j],     ah[mt], bl[j][0], bl[j][1]);
                    mma_bf16(acc[mt][2 * j + 1], ah[mt], bl[j][2], bl[j][3]);
                }
        }
        __syncthreads();
    }

    // fused epilogue: out = front_x + (conv + bf) * S, direct register stores
    const float* Sb = g_S + (size_t)b * HW;
#pragma unroll
    for (int mt = 0; mt < 2; mt++) {
        const int o_lo = m0 + wm * 32 + mt * 16 + (lane >> 2);
        const int o_hi = o_lo + 8;
        const float bi_lo = bf[o_lo], bi_hi = bf[o_hi];
#pragma unroll
        for (int j = 0; j < 8; j++) {
            const int p = n0 + wn * 64 + j * 8 + 2 * (lane & 3);
            const float2 Sv = *(const float2*)&Sb[p];
            const size_t off0 = ((size_t)(b * Cc + o_lo)) * HW + p;
            const size_t off1 = ((size_t)(b * Cc + o_hi)) * HW + p;
            const float2 f0 = *(const float2*)&front_x[off0];
            const float2 f1 = *(const float2*)&front_x[off1];
            float2 r0, r1;
            r0.x = f0.x + (acc[mt][j][0] + bi_lo) * Sv.x;
            r0.y = f0.y + (acc[mt][j][1] + bi_lo) * Sv.y;
            r1.x = f1.x + (acc[mt][j][2] + bi_hi) * Sv.x;
            r1.y = f1.y + (acc[mt][j][3] + bi_hi) * Sv.y;
            *(float2*)&out[off0] = r0;
            *(float2*)&out[off1] = r1;
        }
    }
}

// ===================== launch ==============================================
extern "C" void kernel_launch(void* const* d_in, const int* in_sizes, int n_in,
                              void* d_out, int out_size) {
    const float* front_x     = (const float*)d_in[0];
    const float* cross_x     = (const float*)d_in[1];
    const float* front_x_hat = (const float*)d_in[2];
    const float* Wq = (const float*)d_in[3];
    const float* bq = (const float*)d_in[4];
    const float* Wk = (const float*)d_in[5];
    const float* bk = (const float*)d_in[6];
    const float* Wv = (const float*)d_in[7];
    const float* bv = (const float*)d_in[8];
    const float* Wf = (const float*)d_in[9];
    const float* bf = (const float*)d_in[10];
    float* out = (float*)d_out;

    cudaFuncSetAttribute(conv_mma, cudaFuncAttributeMaxDynamicSharedMemorySize, 3 * STAGE);

    float* vt;
    cudaGetSymbolAddress((void**)&vt, g_vt);

    zero_halo<<<260, 256>>>();
    prep_w<<<512, 256>>>(Wf);

    gemm_qk<<<dim3(32, 2, 4), 256>>>(cross_x, front_x, Wq, bq, Wk, bk);
    gemm1x1_nhwc<<<dim3(32, 8, 4), 256>>>(front_x_hat, Wv, bv, vt);

    energy_argmax<<<dim3(32, 4, 4), 128>>>();
    reduce_argmax<<<64, 256>>>();

    fill_xt<<<dim3(16, 64, 4), 256>>>(front_x);

    conv_mma<<<dim3(32, 2, 4), 256, 3 * STAGE>>>(front_x, bf, out);
}

// round 7
// speedup vs baseline: 2.3327x; 1.1000x over previous
#include <cuda_runtime.h>
#include <cuda_bf16.h>
#include <float.h>
#include <stdint.h>

#define Bb 4
#define Cc 256
#define C8 32
#define Hh 64
#define Ww 64
#define HW 4096

// ===================== helpers =============================================
__device__ __forceinline__ uint32_t smem_u32(const void* p) {
    uint32_t a;
    asm("{ .reg .u64 t; cvta.to.shared.u64 t, %1; cvt.u32.u64 %0, t; }"
        : "=r"(a) : "l"(p));
    return a;
}
#define SWZ128(off) ((off) ^ (((off) >> 3) & 0x70))

__device__ __forceinline__ void ldsm_x4(uint32_t (&r)[4], uint32_t addr) {
    asm volatile("ldmatrix.sync.aligned.m8n8.x4.shared.b16 {%0,%1,%2,%3}, [%4];"
                 : "=r"(r[0]), "=r"(r[1]), "=r"(r[2]), "=r"(r[3]) : "r"(addr));
}

__device__ __forceinline__ void mma_bf16(float (&d)[4], const uint32_t (&a)[4],
                                         uint32_t b0, uint32_t b1) {
    asm volatile(
        "mma.sync.aligned.m16n8k16.row.col.f32.bf16.bf16.f32 "
        "{%0,%1,%2,%3}, {%4,%5,%6,%7}, {%8,%9}, {%0,%1,%2,%3};"
        : "+f"(d[0]), "+f"(d[1]), "+f"(d[2]), "+f"(d[3])
        : "r"(a[0]), "r"(a[1]), "r"(a[2]), "r"(a[3]), "r"(b0), "r"(b1));
}

#define CP_ASYNC16(dst, src) \
    asm volatile("cp.async.cg.shared.global [%0], [%1], 16;" :: "r"(dst), "l"(src) : "memory")
#define CP_COMMIT()  asm volatile("cp.async.commit_group;" ::: "memory")
#define CP_WAIT1()   asm volatile("cp.async.wait_group 1;" ::: "memory")
#define CP_WAIT0()   asm volatile("cp.async.wait_group 0;" ::: "memory")

__device__ __forceinline__ void split_bf16(float v, uint16_t& h, uint16_t& l) {
    __nv_bfloat16 hb = __float2bfloat16_rn(v);
    __nv_bfloat16 lb = __float2bfloat16_rn(v - __bfloat162float(hb));
    h = __bfloat16_as_ushort(hb);
    l = __bfloat16_as_ushort(lb);
}

// ===================== scratch =============================================
__device__ float g_q[Bb * C8 * HW];
__device__ float g_k[Bb * C8 * HW];
__device__ float g_vt[Bb * HW * Cc];          // NHWC value: [b][p][c]
__device__ float g_pmax[Bb * 4 * HW];
__device__ int   g_parg[Bb * 4 * HW];
__device__ float g_S[Bb * HW];
__device__ int   g_arg[Bb * HW];
// NHWC bf16, zero halo: [B][66][66][hi 512 | lo 512]
__device__ __nv_bfloat16 g_Xt[(size_t)Bb * 66 * 66 * 1024];
// conv weights split: [seg(hi0/lo1)][tap9][o 256][c 512] bf16
__device__ __nv_bfloat16 g_Wa[2 * 9 * 256 * 512];
// v weights split: [o 256][c 256] bf16
__device__ __nv_bfloat16 g_Wvh[256 * 256];
__device__ __nv_bfloat16 g_Wvl[256 * 256];

// ===================== fused q+k projection (O=32 each) =====================
__global__ __launch_bounds__(256) void gemm_qk(const float* __restrict__ cross_x,
                                               const float* __restrict__ front_x,
                                               const float* __restrict__ Wq,
                                               const float* __restrict__ bq,
                                               const float* __restrict__ Wk,
                                               const float* __restrict__ bk) {
    __shared__ float Xs[16][128];
    __shared__ float Ws[16][36];
    const int b   = blockIdx.z;
    const int sel = blockIdx.y;                 // 0 -> q, 1 -> k
    const int hw0 = blockIdx.x * 128;
    const int tid = threadIdx.x;
    const int hid = tid & 31;
    const int oid = tid >> 5;

    const float* X    = sel ? front_x : cross_x;
    const float* Wm   = sel ? Wk : Wq;
    const float* bias = sel ? bk : bq;
    float*       out  = sel ? g_k : g_q;

    const float* xb = X + (size_t)b * Cc * HW;
    float acc[4][4];
#pragma unroll
    for (int n = 0; n < 4; n++)
#pragma unroll
        for (int m = 0; m < 4; m++) acc[n][m] = 0.f;

    for (int c0 = 0; c0 < Cc; c0 += 16) {
        __syncthreads();
#pragma unroll
        for (int r = 0; r < 8; r++) {
            int idx = tid + r * 256;
            int cc = idx >> 7, h = idx & 127;
            Xs[cc][h] = xb[(size_t)(c0 + cc) * HW + hw0 + h];
        }
#pragma unroll
        for (int r = 0; r < 2; r++) {
            int idx = tid + r * 256;
            int cc = idx >> 5, o = idx & 31;
            Ws[cc][o] = Wm[(size_t)o * Cc + c0 + cc];
        }
        __syncthreads();
#pragma unroll
        for (int cc = 0; cc < 16; cc++) {
            float4 wv = *(const float4*)&Ws[cc][oid * 4];
            float4 xv = *(const float4*)&Xs[cc][hid * 4];
            float wa[4] = {wv.x, wv.y, wv.z, wv.w};
            float xa[4] = {xv.x, xv.y, xv.z, xv.w};
#pragma unroll
            for (int n = 0; n < 4; n++)
#pragma unroll
                for (int m = 0; m < 4; m++) acc[n][m] += wa[n] * xa[m];
        }
    }
#pragma unroll
    for (int n = 0; n < 4; n++) {
        int o = oid * 4 + n;
        float bi = bias[o];
        float4 res;
        res.x = acc[n][0] + bi;
        res.y = acc[n][1] + bi;
        res.z = acc[n][2] + bi;
        res.w = acc[n][3] + bi;
        *(float4*)&out[(size_t)b * C8 * HW + (size_t)o * HW + hw0 + hid * 4] = res;
    }
}

// ===================== v projection: split-bf16 mma.sync ===================
// D[128 o][128 px] per CTA; K=256 in 4 chunks of 64. A = Wv planes (cp.async),
// B = front_x_hat LDG fp32 -> split -> STS ([px][ch] SW128). Epilogue: padded
// smem transpose -> coalesced NHWC fp32 store into g_vt (with bias).
__global__ __launch_bounds__(256) void v_mma(const float* __restrict__ X,
                                             const float* __restrict__ bias,
                                             float* __restrict__ vt) {
    extern __shared__ char dynsm[];
    const int tid  = threadIdx.x;
    const int lane = tid & 31;
    const int wid  = tid >> 5;
    const int wm   = wid & 3;
    const int wn   = wid >> 2;
    const int n0   = blockIdx.x * 128;
    const int m0   = blockIdx.y * 128;
    const int b    = blockIdx.z;

    const uint32_t smbase = smem_u32(dynsm);
    const uint32_t tBhi = smbase, tBlo = smbase + 16384;
    const uint32_t tAhi = smbase + 32768, tAlo = smbase + 49152;

    float acc[2][8][4];
#pragma unroll
    for (int mt = 0; mt < 2; mt++)
#pragma unroll
        for (int j = 0; j < 8; j++)
#pragma unroll
            for (int e = 0; e < 4; e++) acc[mt][j][e] = 0.f;

    const int arow  = wm * 32 + (lane & 15);
    const int acolh = (lane >> 4) * 16;
    const int brow  = wn * 64 + (lane & 7) + ((lane >> 4) << 3);
    const int bcolh = ((lane >> 3) & 1) * 16;
    const int c2    = tid >> 5;                  // 0..7 (ch-pair group)

    for (int s = 0; s < 4; s++) {
        const int kc = s * 64;
        __syncthreads();
        // A tiles via cp.async
#pragma unroll
        for (int i = 0; i < 8; i++) {
            const int t = i >> 2;
            const int c = ((i & 3) << 8) + tid;
            const int r = c >> 3, c16 = c & 7;
            uint32_t dst = (t ? tAlo : tAhi) + SWZ128((uint32_t)(r * 128 + c16 * 16));
            const __nv_bfloat16* src = (t ? g_Wvl : g_Wvh) + (size_t)(m0 + r) * 256 + kc + c16 * 8;
            CP_ASYNC16(dst, src);
        }
        CP_COMMIT();
        // B tiles: LDG fp32 (coalesced over px) -> split -> STS [px][ch]
#pragma unroll
        for (int cc = 0; cc < 4; cc++) {
            const int cp = c2 + 8 * cc;          // ch pair 0..31
            const size_t row0 = ((size_t)b * Cc + kc + 2 * cp) * HW + n0;
#pragma unroll
            for (int pb = 0; pb < 4; pb++) {
                const int px = lane + 32 * pb;
                float v0 = X[row0 + px];
                float v1 = X[row0 + HW + px];
                uint16_t h0, l0, h1, l1;
                split_bf16(v0, h0, l0);
                split_bf16(v1, h1, l1);
                uint32_t off = SWZ128((uint32_t)(px * 128 + cp * 4));
                *(uint32_t*)(dynsm + off)         = (uint32_t)h0 | ((uint32_t)h1 << 16);
                *(uint32_t*)(dynsm + 16384 + off) = (uint32_t)l0 | ((uint32_t)l1 << 16);
            }
        }
        CP_WAIT0();
        __syncthreads();

#pragma unroll
        for (int ks = 0; ks < 4; ks++) {
            uint32_t ah[2][4], al[2][4], bh[4][4], bl[4][4];
#pragma unroll
            for (int mt = 0; mt < 2; mt++) {
                uint32_t off = SWZ128((uint32_t)((arow + mt * 16) * 128 + ks * 32 + acolh));
                ldsm_x4(ah[mt], tAhi + off);
                ldsm_x4(al[mt], tAlo + off);
            }
#pragma unroll
            for (int j = 0; j < 4; j++) {
                uint32_t off = SWZ128((uint32_t)((brow + j * 16) * 128 + ks * 32 + bcolh));
                ldsm_x4(bh[j], tBhi + off);
                ldsm_x4(bl[j], tBlo + off);
            }
#pragma unroll
            for (int mt = 0; mt < 2; mt++)
#pragma unroll
                for (int j = 0; j < 4; j++) {
                    mma_bf16(acc[mt][2 * j],     ah[mt], bh[j][0], bh[j][1]);
                    mma_bf16(acc[mt][2 * j + 1], ah[mt], bh[j][2], bh[j][3]);
                    mma_bf16(acc[mt][2 * j],     al[mt], bh[j][0], bh[j][1]);
                    mma_bf16(acc[mt][2 * j + 1], al[mt], bh[j][2], bh[j][3]);
                    mma_bf16(acc[mt][2 * j],     ah[mt], bl[j][0], bl[j][1]);
                    mma_bf16(acc[mt][2 * j + 1], ah[mt], bl[j][2], bl[j][3]);
                }
        }
    }

    // epilogue: transpose through padded smem (row stride 132 floats)
    __syncthreads();
    float* smep = (float*)dynsm;
#pragma unroll
    for (int mt = 0; mt < 2; mt++) {
        const int o_lo = wm * 32 + mt * 16 + (lane >> 2);
        const int o_hi = o_lo + 8;
        const float bi_lo = bias[m0 + o_lo], bi_hi = bias[m0 + o_hi];
#pragma unroll
        for (int j = 0; j < 8; j++) {
            const int p = wn * 64 + j * 8 + 2 * (lane & 3);
            smep[p * 132 + o_lo]       = acc[mt][j][0] + bi_lo;
            smep[(p + 1) * 132 + o_lo] = acc[mt][j][1] + bi_lo;
            smep[p * 132 + o_hi]       = acc[mt][j][2] + bi_hi;
            smep[(p + 1) * 132 + o_hi] = acc[mt][j][3] + bi_hi;
        }
    }
    __syncthreads();
    // coalesced store: each warp writes 16 px rows of 128 floats
#pragma unroll
    for (int r = 0; r < 16; r++) {
        const int p = wid + 8 * r;
        float4 v = *(const float4*)&smep[p * 132 + lane * 4];
        *(float4*)&vt[((size_t)b * HW + n0 + p) * Cc + m0 + lane * 4] = v;
    }
}

// ===================== energy rowmax/argmax (exact fp32) ====================
__global__ __launch_bounds__(128) void energy_argmax() {
    __shared__ float ks[32][128];
    const int b  = blockIdx.y;
    const int j  = blockIdx.x * 128 + threadIdx.x;
    const int sp = blockIdx.z;
    const float* qb = g_q + (size_t)b * C8 * HW;
    const float* kb = g_k + (size_t)b * C8 * HW;

    float qr[32];
#pragma unroll
    for (int c = 0; c < 32; c++) qr[c] = qb[c * HW + j];

    float best = -FLT_MAX;
    int   barg = 0;
    const int i0base = sp * 1024;

    for (int it = 0; it < 8; it++) {
        int i0 = i0base + it * 128;
        __syncthreads();
#pragma unroll
        for (int c = 0; c < 32; c++) ks[c][threadIdx.x] = kb[c * HW + i0 + threadIdx.x];
        __syncthreads();
#pragma unroll 4
        for (int ii = 0; ii < 128; ii += 4) {
            float a0 = 0.f, a1 = 0.f, a2 = 0.f, a3 = 0.f;
#pragma unroll
            for (int c = 0; c < 32; c++) {
                float4 kv = *(const float4*)&ks[c][ii];
                a0 += kv.x * qr[c];
                a1 += kv.y * qr[c];
                a2 += kv.z * qr[c];
                a3 += kv.w * qr[c];
            }
            if (a0 > best) { best = a0; barg = i0 + ii; }
            if (a1 > best) { best = a1; barg = i0 + ii + 1; }
            if (a2 > best) { best = a2; barg = i0 + ii + 2; }
            if (a3 > best) { best = a3; barg = i0 + ii + 3; }
        }
    }
    g_pmax[((size_t)b * 4 + sp) * HW + j] = best;
    g_parg[((size_t)b * 4 + sp) * HW + j] = barg;
}

__global__ void reduce_argmax() {
    int t = blockIdx.x * 256 + threadIdx.x;
    if (t >= Bb * HW) return;
    int b = t >> 12, j = t & 4095;
    float best = g_pmax[((size_t)b * 4) * HW + j];
    int   arg  = g_parg[((size_t)b * 4) * HW + j];
#pragma unroll
    for (int sp = 1; sp < 4; sp++) {
        float e = g_pmax[((size_t)b * 4 + sp) * HW + j];
        if (e > best) { best = e; arg = g_parg[((size_t)b * 4 + sp) * HW + j]; }
    }
    g_S[t] = best;
    g_arg[t] = arg;
}

// ===================== conv input prep =====================================
__global__ void zero_halo() {
    const int t = blockIdx.x * 256 + threadIdx.x;    // 4*260*64 = 66560
    if (t >= Bb * 260 * 64) return;
    const int u = t & 63;
    const int pix = (t >> 6) % 260;
    const int b = t / (260 * 64);
    int y, x;
    if (pix < 66)       { y = 0;        x = pix; }
    else if (pix < 132) { y = 65;       x = pix - 66; }
    else if (pix < 196) { y = pix - 131; x = 0; }
    else                { y = pix - 195; x = 65; }
    ((uint4*)g_Xt)[(((size_t)(b * 66 + y) * 66 + x) << 7) + u] = make_uint4(0, 0, 0, 0);
}

__global__ __launch_bounds__(256) void fill_xt(const float* __restrict__ front_x) {
    __shared__ float sm[32][65];
    const int c0 = blockIdx.x * 32;
    const int y  = blockIdx.y;
    const int b  = blockIdx.z;
    const int tid = threadIdx.x;
    const int x  = tid >> 2;
    const int g  = tid & 3;

    float vals[8];
    if (c0 < 256) {
#pragma unroll
        for (int pass = 0; pass < 8; pass++) {
            int idx = tid + pass * 256;
            int cc = idx >> 6, xx = idx & 63;
            sm[cc][xx] = front_x[((size_t)b * Cc + c0 + cc) * HW + y * Ww + xx];
        }
        __syncthreads();
#pragma unroll
        for (int e = 0; e < 8; e++) vals[e] = sm[g * 8 + e][x];
    } else {
        const int a = g_arg[b * HW + y * Ww + x];
        const float* vp = g_vt + ((size_t)b * HW + a) * Cc + (c0 - 256) + g * 8;
        float4 u0 = *(const float4*)vp;
        float4 u1 = *(const float4*)(vp + 4);
        vals[0] = u0.x; vals[1] = u0.y; vals[2] = u0.z; vals[3] = u0.w;
        vals[4] = u1.x; vals[5] = u1.y; vals[6] = u1.z; vals[7] = u1.w;
    }

    uint32_t hu[4], lu[4];
#pragma unroll
    for (int e = 0; e < 4; e++) {
        uint16_t h0, l0, h1, l1;
        split_bf16(vals[e * 2], h0, l0);
        split_bf16(vals[e * 2 + 1], h1, l1);
        hu[e] = (uint32_t)h0 | ((uint32_t)h1 << 16);
        lu[e] = (uint32_t)l0 | ((uint32_t)l1 << 16);
    }
    size_t base = ((size_t)(b * 66 + y + 1) * 66 + (x + 1)) * 1024 + c0 + g * 8;
    *(uint4*)&g_Xt[base]       = make_uint4(hu[0], hu[1], hu[2], hu[3]);
    *(uint4*)&g_Xt[base + 512] = make_uint4(lu[0], lu[1], lu[2], lu[3]);
}

// conv weights: Wf(O=256, I=512, 3,3) -> g_Wa[seg][tap][o][i] bf16 hi/lo
__global__ void prep_w(const float* __restrict__ Wf) {
    int t = blockIdx.x * 256 + threadIdx.x;       // 131072
    int o = t >> 9, i = t & 511;
#pragma unroll
    for (int k = 0; k < 9; k++) {
        float w = Wf[((size_t)o * 512 + i) * 9 + k];
        uint16_t h, l;
        split_bf16(w, h, l);
        g_Wa[(((size_t)0 * 9 + k) * 256 + o) * 512 + i] = __ushort_as_bfloat16(h);
        g_Wa[(((size_t)1 * 9 + k) * 256 + o) * 512 + i] = __ushort_as_bfloat16(l);
    }
}

// v weights: Wv(256,256) -> hi/lo planes
__global__ void prep_wv(const float* __restrict__ Wv) {
    int t = blockIdx.x * 256 + threadIdx.x;       // 65536
    uint16_t h, l;
    split_bf16(Wv[t], h, l);
    g_Wvh[t] = __ushort_as_bfloat16(h);
    g_Wvl[t] = __ushort_as_bfloat16(l);
}

// ===================== mma.sync conv3x3 + fused epilogue ====================
#define STAGE 65536
#define NCHUNK 72

__device__ __forceinline__ void stage_chunk(uint32_t stg, int s, int b, int y0, int m0) {
    const int tap = s >> 3, kc = (s & 7) * 64;
    const int dy = tap / 3, dx = tap % 3;
    const int tid = threadIdx.x;
#pragma unroll
    for (int i = 0; i < 16; i++) {
        const int t = i >> 2;                         // 0:Bhi 1:Blo 2:Ahi 3:Alo
        const int c = ((i & 3) << 8) + tid;           // 0..1023
        const int r = c >> 3, c16 = c & 7;
        uint32_t dst = stg + (uint32_t)(t * 16384) + SWZ128((uint32_t)(r * 128 + c16 * 16));
        const void* src;
        if (t < 2) {
            const int ry = r >> 6, x = r & 63;
            src = &g_Xt[(((size_t)(b * 66 + y0 + ry + dy) * 66) + (x + dx)) * 1024
                        + t * 512 + kc + c16 * 8];
        } else {
            src = &g_Wa[(((size_t)((t - 2) * 9 + tap) * 256) + m0 + r) * 512 + kc + c16 * 8];
        }
        CP_ASYNC16(dst, src);
    }
    CP_COMMIT();
}

__global__ __launch_bounds__(256, 1) void conv_mma(const float* __restrict__ front_x,
                                                   const float* __restrict__ bf,
                                                   float* __restrict__ out) {
    extern __shared__ char dynsm[];
    const int tid  = threadIdx.x;
    const int lane = tid & 31;
    const int wid  = tid >> 5;
    const int wm   = wid & 3;
    const int wn   = wid >> 2;
    const int nt   = blockIdx.x;
    const int m0   = blockIdx.y * 128;
    const int b    = blockIdx.z;
    const int y0   = nt * 2;
    const int n0   = nt * 128;

    const uint32_t smbase = smem_u32(dynsm);

    float acc[2][8][4];
#pragma unroll
    for (int mt = 0; mt < 2; mt++)
#pragma unroll
        for (int j = 0; j < 8; j++)
#pragma unroll
            for (int e = 0; e < 4; e++) acc[mt][j][e] = 0.f;

    const int arow  = wm * 32 + (lane & 15);
    const int acolh = (lane >> 4) * 16;
    const int brow  = wn * 64 + (lane & 7) + ((lane >> 4) << 3);
    const int bcolh = ((lane >> 3) & 1) * 16;

    stage_chunk(smbase, 0, b, y0, m0);
    stage_chunk(smbase + STAGE, 1, b, y0, m0);

    for (int s = 0; s < NCHUNK; s++) {
        CP_WAIT1();
        __syncthreads();
        if (s + 2 < NCHUNK)
            stage_chunk(smbase + ((s + 2) % 3) * STAGE, s + 2, b, y0, m0);

        const uint32_t base = smbase + (s % 3) * STAGE;
        const uint32_t tBhi = base, tBlo = base + 16384;
        const uint32_t tAhi = base + 32768, tAlo = base + 49152;

#pragma unroll
        for (int ks = 0; ks < 4; ks++) {
            uint32_t ah[2][4], al[2][4], bh[4][4], bl[4][4];
#pragma unroll
            for (int mt = 0; mt < 2; mt++) {
                uint32_t off = SWZ128((uint32_t)((arow + mt * 16) * 128 + ks * 32 + acolh));
                ldsm_x4(ah[mt], tAhi + off);
                ldsm_x4(al[mt], tAlo + off);
            }
#pragma unroll
            for (int j = 0; j < 4; j++) {
                uint32_t off = SWZ128((uint32_t)((brow + j * 16) * 128 + ks * 32 + bcolh));
                ldsm_x4(bh[j], tBhi + off);
                ldsm_x4(bl[j], tBlo + off);
            }
#pragma unroll
            for (int mt = 0; mt < 2; mt++)
#pragma unroll
                for (int j = 0; j < 4; j++) {
                    mma_bf16(acc[mt][2 * j],     ah[mt], bh[j][0], bh[j][1]);
                    mma_bf16(acc[mt][2 * j + 1], ah[mt], bh[j][2], bh[j][3]);
                    mma_bf16(acc[mt][2 * j],     al[mt], bh[j][0], bh[j][1]);
                    mma_bf16(acc[mt][2 * j + 1], al[mt], bh[j][2], bh[j][3]);
                    mma_bf16(acc[mt][2 * j],     ah[mt], bl[j][0], bl[j][1]);
                    mma_bf16(acc[mt][2 * j + 1], ah[mt], bl[j][2], bl[j][3]);
                }
        }
        __syncthreads();
    }

    const float* Sb = g_S + (size_t)b * HW;
#pragma unroll
    for (int mt = 0; mt < 2; mt++) {
        const int o_lo = m0 + wm * 32 + mt * 16 + (lane >> 2);
        const int o_hi = o_lo + 8;
        const float bi_lo = bf[o_lo], bi_hi = bf[o_hi];
#pragma unroll
        for (int j = 0; j < 8; j++) {
            const int p = n0 + wn * 64 + j * 8 + 2 * (lane & 3);
            const float2 Sv = *(const float2*)&Sb[p];
            const size_t off0 = ((size_t)(b * Cc + o_lo)) * HW + p;
            const size_t off1 = ((size_t)(b * Cc + o_hi)) * HW + p;
            const float2 f0 = *(const float2*)&front_x[off0];
            const float2 f1 = *(const float2*)&front_x[off1];
            float2 r0, r1;
            r0.x = f0.x + (acc[mt][j][0] + bi_lo) * Sv.x;
            r0.y = f0.y + (acc[mt][j][1] + bi_lo) * Sv.y;
            r1.x = f1.x + (acc[mt][j][2] + bi_hi) * Sv.x;
            r1.y = f1.y + (acc[mt][j][3] + bi_hi) * Sv.y;
            *(float2*)&out[off0] = r0;
            *(float2*)&out[off1] = r1;
        }
    }
}

// ===================== launch ==============================================
extern "C" void kernel_launch(void* const* d_in, const int* in_sizes, int n_in,
                              void* d_out, int out_size) {
    const float* front_x     = (const float*)d_in[0];
    const float* cross_x     = (const float*)d_in[1];
    const float* front_x_hat = (const float*)d_in[2];
    const float* Wq = (const float*)d_in[3];
    const float* bq = (const float*)d_in[4];
    const float* Wk = (const float*)d_in[5];
    const float* bk = (const float*)d_in[6];
    const float* Wv = (const float*)d_in[7];
    const float* bv = (const float*)d_in[8];
    const float* Wf = (const float*)d_in[9];
    const float* bf = (const float*)d_in[10];
    float* out = (float*)d_out;

    cudaFuncSetAttribute(conv_mma, cudaFuncAttributeMaxDynamicSharedMemorySize, 3 * STAGE);
    cudaFuncSetAttribute(v_mma, cudaFuncAttributeMaxDynamicSharedMemorySize, 128 * 132 * 4);

    float* vt;
    cudaGetSymbolAddress((void**)&vt, g_vt);

    zero_halo<<<260, 256>>>();
    prep_w<<<512, 256>>>(Wf);
    prep_wv<<<256, 256>>>(Wv);

    gemm_qk<<<dim3(32, 2, 4), 256>>>(cross_x, front_x, Wq, bq, Wk, bk);
    v_mma<<<dim3(32, 2, 4), 256, 128 * 132 * 4>>>(front_x_hat, bv, vt);

    energy_argmax<<<dim3(32, 4, 4), 128>>>();
    reduce_argmax<<<64, 256>>>();

    fill_xt<<<dim3(16, 64, 4), 256>>>(front_x);

    conv_mma<<<dim3(32, 2, 4), 256, 3 * STAGE>>>(front_x, bf, out);
}